// round 4
// baseline (speedup 1.0000x reference)
#include <cuda_runtime.h>
#include <cuda_bf16.h>
#include <cstdint>

// ---------------------------------------------------------------- dims
#define BB   512
#define FP   4096
#define ENCD 64
#define HH   512
#define VV   42
#define SEQL 128
#define H3   1536
#define NA   2090    // fused phase-A output rows: 2048 gates + 42 out
#define NB   2048
#define KC   1024    // concatenated K
#define GRID_N 148

// ---------------------------------------------------------------- fp32 scratch
#define F_MU   0u
#define F_LV   32768u
#define F_H0F  65536u
#define F_H1F  327680u
#define F_WF   589824u
#define F_BFV  1376256u
#define F_BA0  1377792u
#define F_BA1  1379904u
#define F_BB2  1382016u
#define F_TOTAL 1384064u
__device__ __align__(256) float g_f32[F_TOTAL];

// ---------------------------------------------------------------- bf16 scratch
#define S_XS     0ull
#define S_E1WS   4194304ull
#define S_H1ES   20971520ull
#define S_E2WS   23068672ull
#define S_H2ES   27262976ull
#define S_E3WS   28311552ull
#define S_H3ES   29360128ull
#define S_E41S   29884416ull
#define S_E42S   29949952ull
#define S_ENCS   30015488ull
#define S_DFC1S  30081024ull
#define S_WA     30146560ull   // [2090, 2048]
#define S_WB     34426880ull   // [2048, 2048]
#define S_AA0    38621184ull   // [512, 2048]
#define S_AA1    39669760ull
#define S_AB0    40718336ull
#define S_AB1    41766912ull
#define S_TOTAL  42815488ull
__device__ __align__(256) __nv_bfloat16 g_bf[S_TOTAL];

// barrier state
__device__ int g_bar_cnt;
__device__ volatile unsigned g_bar_gen;

// ---------------------------------------------------------------- PTX helpers
__device__ __forceinline__ uint32_t smem_u32(const void* p) {
    uint32_t a;
    asm("{ .reg .u64 t; cvta.to.shared.u64 t, %1; cvt.u32.u64 %0, t; }" : "=r"(a) : "l"(p));
    return a;
}
__device__ __forceinline__ void cp16(uint32_t dst, const void* src) {
    asm volatile("cp.async.cg.shared.global [%0], [%1], 16;\n" :: "r"(dst), "l"(src));
}
__device__ __forceinline__ void cp16z(uint32_t dst, const void* src, int sz) {
    asm volatile("cp.async.cg.shared.global [%0], [%1], 16, %2;\n"
                 :: "r"(dst), "l"(src), "r"(sz));
}
__device__ __forceinline__ void ldm4(uint32_t* r, uint32_t addr) {
    asm volatile("ldmatrix.sync.aligned.m8n8.x4.shared.b16 {%0,%1,%2,%3}, [%4];\n"
                 : "=r"(r[0]), "=r"(r[1]), "=r"(r[2]), "=r"(r[3]) : "r"(addr));
}
__device__ __forceinline__ void mma16816(float* c, const uint32_t* a, uint32_t b0, uint32_t b1) {
    asm volatile(
        "mma.sync.aligned.m16n8k16.row.col.f32.bf16.bf16.f32 "
        "{%0,%1,%2,%3}, {%4,%5,%6,%7}, {%8,%9}, {%0,%1,%2,%3};\n"
        : "+f"(c[0]), "+f"(c[1]), "+f"(c[2]), "+f"(c[3])
        : "r"(a[0]), "r"(a[1]), "r"(a[2]), "r"(a[3]), "r"(b0), "r"(b1));
}
__device__ __forceinline__ float sigf(float x) { return 1.f / (1.f + expf(-x)); }

#define ROWB 80
#define STB  ((64 + 128) * ROWB)   // 15360
#define PERSIST_SMEM (3 * STB)     // 46080

// ---------------------------------------------------------------- grid barrier
__device__ __forceinline__ void grid_bar() {
    __syncthreads();
    if (threadIdx.x == 0) {
        unsigned gen = g_bar_gen;
        __threadfence();
        if (atomicAdd(&g_bar_cnt, 1) == GRID_N - 1) {
            atomicExch(&g_bar_cnt, 0);
            __threadfence();
            g_bar_gen = gen + 1;
        } else {
            while (g_bar_gen == gen) { __nanosleep(32); }
            __threadfence();
        }
    }
    __syncthreads();
}

// ---------------------------------------------------------------- 64x128 tile GEMM core
// A: [512, 2048] bf16 (hi cols 0:1024, lo 1024:2048), W: [Nvalid rows, 2048] same.
// K'=3072 via segments: seg0 Ah*Wh, seg1 Al*Wh, seg2 Ah*Wl.
__device__ void gemm_tile(const __nv_bfloat16* __restrict__ A,
                          const __nv_bfloat16* __restrict__ W,
                          int Nvalid, int m0, int n0,
                          uint32_t sb, int tid, float acc[2][4][4]) {
    const int lane = tid & 31, wid = tid >> 5;
    const int wmBase = (wid >> 2) * 32;
    const int wnBase = (wid & 3) * 32;

#pragma unroll
    for (int mi = 0; mi < 2; mi++)
#pragma unroll
        for (int ni = 0; ni < 4; ni++)
#pragma unroll
            for (int q = 0; q < 4; q++) acc[mi][ni][q] = 0.f;

    auto issue = [&](int kt) {
        const int seg = kt >> 5;
        const int kk = kt & 31;
        const int aCol = kk * 32 + (seg == 1 ? KC : 0);
        const int bCol = kk * 32 + (seg == 2 ? KC : 0);
        const int st = kt % 3;
        const uint32_t sA = sb + st * STB;
        const uint32_t sB = sA + 64 * ROWB;
        {
            int row = tid >> 2, ch = tid & 3;
            cp16(sA + row * ROWB + ch * 16,
                 A + (size_t)(m0 + row) * (2 * KC) + aCol + ch * 8);
        }
#pragma unroll
        for (int j = 0; j < 2; j++) {
            int v = tid * 2 + j;
            int row = v >> 2, ch = v & 3;
            int n = n0 + row;
            int ok = (n < Nvalid);
            cp16z(sB + row * ROWB + ch * 16,
                  W + (size_t)(ok ? n : 0) * (2 * KC) + bCol + ch * 8,
                  ok ? 16 : 0);
        }
        asm volatile("cp.async.commit_group;\n" ::: "memory");
    };

    issue(0);
    issue(1);
    for (int kt = 0; kt < 96; kt++) {
        asm volatile("cp.async.wait_group 1;\n" ::: "memory");
        __syncthreads();
        if (kt + 2 < 96) issue(kt + 2);
        else asm volatile("cp.async.commit_group;\n" ::: "memory");

        const int st = kt % 3;
        const uint32_t sA = sb + st * STB;
        const uint32_t sB = sA + 64 * ROWB;
#pragma unroll
        for (int kh = 0; kh < 2; kh++) {
            uint32_t a[2][4], b[2][4];
#pragma unroll
            for (int mi = 0; mi < 2; mi++) {
                uint32_t addr = sA + (wmBase + mi * 16 + (lane & 15)) * ROWB
                              + kh * 32 + ((lane >> 4) * 16);
                ldm4(a[mi], addr);
            }
#pragma unroll
            for (int nj = 0; nj < 2; nj++) {
                int grp = lane >> 3;
                int nrow = wnBase + nj * 16 + ((grp >> 1) * 8) + (lane & 7);
                uint32_t addr = sB + nrow * ROWB + (kh * 16 + (grp & 1) * 8) * 2;
                ldm4(b[nj], addr);
            }
#pragma unroll
            for (int mi = 0; mi < 2; mi++)
#pragma unroll
                for (int ni = 0; ni < 4; ni++)
                    mma16816(acc[mi][ni], a[mi],
                             b[ni >> 1][(ni & 1) * 2], b[ni >> 1][(ni & 1) * 2 + 1]);
        }
    }
    __syncthreads();
}

// ---------------------------------------------------------------- epilogues
// Gate rows interleaved per j: 4j+0=r(pre), 4j+1=z(pre), 4j+2=gi_n, 4j+3=gh_n.
// Even lanes hold (r,z); odd lanes hold (gi_n, gh_n) for the same (m, j).
__device__ void epi_combine(float acc[2][4][4], const float* __restrict__ bias,
                            int m0, int n0, float* __restrict__ hf,
                            __nv_bfloat16* __restrict__ dst1,
                            __nv_bfloat16* __restrict__ dst2, int tid) {
    const int lane = tid & 31, wid = tid >> 5;
    const int wmBase = (wid >> 2) * 32;
    const int wnBase = (wid & 3) * 32;
    const bool odd = lane & 1;
#pragma unroll
    for (int mi = 0; mi < 2; mi++)
#pragma unroll
        for (int ni = 0; ni < 4; ni++) {
            const int coln = n0 + wnBase + ni * 8 + (lane & 3) * 2;
            const float b0 = bias[coln], b1 = bias[coln + 1];
#pragma unroll
            for (int half = 0; half < 2; half++) {
                const int mm = m0 + wmBase + mi * 16 + (lane >> 2) + half * 8;
                float c0 = acc[mi][ni][half * 2 + 0] + b0;
                float c1 = acc[mi][ni][half * 2 + 1] + b1;
                float s0 = sigf(c0);                                  // even: sig(r)
                float rr = __shfl_xor_sync(0xffffffffu, s0, 1);       // odd gets r
                float nv = tanhf(c0 + rr * c1);                       // odd: n
                float zz = sigf(c1);                                  // even: z
                float zo = __shfl_xor_sync(0xffffffffu, zz, 1);       // odd gets z
                if (odd) {
                    int j = coln >> 2;
                    float hp = hf[mm * HH + j];
                    float h = (1.f - zo) * nv + zo * hp;
                    hf[mm * HH + j] = h;
                    __nv_bfloat16 hi = __float2bfloat16(h);
                    __nv_bfloat16 lo = __float2bfloat16(h - __bfloat162float(hi));
                    dst1[(size_t)mm * (2 * KC) + j] = hi;
                    dst1[(size_t)mm * (2 * KC) + KC + j] = lo;
                    dst2[(size_t)mm * (2 * KC) + j] = hi;
                    dst2[(size_t)mm * (2 * KC) + KC + j] = lo;
                }
            }
        }
}

__device__ void epi_out(float acc[2][4][4], const float* __restrict__ biasO,
                        int m0, float* __restrict__ outp, int tOut, int tid) {
    const int lane = tid & 31, wid = tid >> 5;
    const int wmBase = (wid >> 2) * 32;
    const int wnBase = (wid & 3) * 32;
#pragma unroll
    for (int mi = 0; mi < 2; mi++)
#pragma unroll
        for (int ni = 0; ni < 4; ni++) {
            const int v = wnBase + ni * 8 + (lane & 3) * 2;
#pragma unroll
            for (int half = 0; half < 2; half++) {
                const int mm = m0 + wmBase + mi * 16 + (lane >> 2) + half * 8;
                if (v < VV)
                    outp[(size_t)mm * (SEQL * VV) + tOut * VV + v] =
                        acc[mi][ni][half * 2] + biasO[v];
                if (v + 1 < VV)
                    outp[(size_t)mm * (SEQL * VV) + tOut * VV + v + 1] =
                        acc[mi][ni][half * 2 + 1] + biasO[v + 1];
            }
        }
}

// ---------------------------------------------------------------- persistent decoder
struct PersistArgs {
    const __nv_bfloat16 *WA, *WB;
    __nv_bfloat16 *AA0, *AA1, *AB0, *AB1;
    const float *bA0, *bA1, *bB;
    float *h0f, *h1f;
    float *outp;
};

__global__ void __launch_bounds__(256) decoder_persist(PersistArgs p) {
    extern __shared__ __align__(128) char smbuf[];
    const uint32_t sb = smem_u32(smbuf);
    const int tid = threadIdx.x;
    const int cid = blockIdx.x;
    float acc[2][4][4];

    __nv_bfloat16* AA[2] = {p.AA0, p.AA1};
    __nv_bfloat16* AB[2] = {p.AB0, p.AB1};

    const int am = cid & 7, an = cid >> 3;   // phase A tile (valid cid<136)
    const int bm = cid & 7, bn = cid >> 3;   // phase B tile (valid cid<128)

    for (int t = 0; t < SEQL; t++) {
        const int cur = t & 1, nxt = cur ^ 1;
        if (cid < 136 && !(an == 16 && t == 0)) {
            gemm_tile(AA[cur], p.WA, NA, am * 64, an * 128, sb, tid, acc);
            if (an < 16)
                epi_combine(acc, (t == 0 ? p.bA0 : p.bA1), am * 64, an * 128,
                            p.h0f, AB[cur], AA[nxt] + 512, tid);
            else
                epi_out(acc, p.bA1 + 2048, am * 64, p.outp, t - 1, tid);
        }
        grid_bar();
        if (cid < 128) {
            gemm_tile(AB[cur], p.WB, NB, bm * 64, bn * 128, sb, tid, acc);
            epi_combine(acc, p.bB, bm * 64, bn * 128,
                        p.h1f, AA[nxt], AB[nxt] + 512, tid);
        }
        grid_bar();
    }
    // out_{127}: SEQL is even -> state buffers at parity 0
    if (cid < 136 && an == 16) {
        gemm_tile(AA[0], p.WA, NA, am * 64, an * 128, sb, tid, acc);
        epi_out(acc, p.bA1 + 2048, am * 64, p.outp, SEQL - 1, tid);
    }
}

// ---------------------------------------------------------------- encoder GEMM (R3 engine)
struct Chunk {
    const __nv_bfloat16* A;
    const __nv_bfloat16* W;
    const float* bias;
    float* C;
    __nv_bfloat16* Cs;
    int N;
    int ldc;
    int mode;   // 1=fp32 out, 2=split out, 4=relu
    int ntiles;
};
struct GemmArgs {
    Chunk ch[2];
    int K;
};

__global__ void __launch_bounds__(256) gemm_mma64(GemmArgs args) {
    constexpr int BM = 64;
    constexpr int STB64 = (BM + 128) * ROWB;
    extern __shared__ __align__(128) char smbuf[];
    const uint32_t sb = smem_u32(smbuf);
    const int tid = threadIdx.x;
    const int lane = tid & 31, wid = tid >> 5;
    const int wmBase = (wid >> 2) * 32;
    const int wnBase = (wid & 3) * 32;

    int rem = blockIdx.y, ci = 0;
    while (rem >= args.ch[ci].ntiles) { rem -= args.ch[ci].ntiles; ci++; }
    const Chunk c = args.ch[ci];
    const int n0 = rem * 128;
    const int m0 = blockIdx.x * BM;
    const int K = args.K;
    const int ksub = K >> 5;
    const int Kt = 3 * ksub;
    const int ld2 = 2 * K;

    auto issue = [&](int kt) {
        const int seg = kt / ksub;
        const int kk = kt - seg * ksub;
        const int aCol = kk * 32 + (seg == 1 ? K : 0);
        const int bCol = kk * 32 + (seg == 2 ? K : 0);
        const int st = kt % 3;
        const uint32_t sA = sb + st * STB64;
        const uint32_t sB = sA + BM * ROWB;
        {
            int row = tid >> 2, ch = tid & 3;
            cp16(sA + row * ROWB + ch * 16,
                 c.A + (size_t)(m0 + row) * ld2 + aCol + ch * 8);
        }
#pragma unroll
        for (int j = 0; j < 2; j++) {
            int v = tid * 2 + j;
            int row = v >> 2, ch = v & 3;
            int n = n0 + row;
            int ok = (n < c.N);
            cp16z(sB + row * ROWB + ch * 16,
                  c.W + (size_t)(ok ? n : 0) * ld2 + bCol + ch * 8, ok ? 16 : 0);
        }
        asm volatile("cp.async.commit_group;\n" ::: "memory");
    };

    float acc[2][4][4];
#pragma unroll
    for (int mi = 0; mi < 2; mi++)
#pragma unroll
        for (int ni = 0; ni < 4; ni++)
#pragma unroll
            for (int q = 0; q < 4; q++) acc[mi][ni][q] = 0.f;

    issue(0); issue(1);
    for (int kt = 0; kt < Kt; kt++) {
        asm volatile("cp.async.wait_group 1;\n" ::: "memory");
        __syncthreads();
        if (kt + 2 < Kt) issue(kt + 2);
        else asm volatile("cp.async.commit_group;\n" ::: "memory");

        const int st = kt % 3;
        const uint32_t sA = sb + st * STB64;
        const uint32_t sB = sA + BM * ROWB;
#pragma unroll
        for (int kh = 0; kh < 2; kh++) {
            uint32_t a[2][4], b[2][4];
#pragma unroll
            for (int mi = 0; mi < 2; mi++) {
                uint32_t addr = sA + (wmBase + mi * 16 + (lane & 15)) * ROWB
                              + kh * 32 + ((lane >> 4) * 16);
                ldm4(a[mi], addr);
            }
#pragma unroll
            for (int nj = 0; nj < 2; nj++) {
                int grp = lane >> 3;
                int nrow = wnBase + nj * 16 + ((grp >> 1) * 8) + (lane & 7);
                uint32_t addr = sB + nrow * ROWB + (kh * 16 + (grp & 1) * 8) * 2;
                ldm4(b[nj], addr);
            }
#pragma unroll
            for (int mi = 0; mi < 2; mi++)
#pragma unroll
                for (int ni = 0; ni < 4; ni++)
                    mma16816(acc[mi][ni], a[mi],
                             b[ni >> 1][(ni & 1) * 2], b[ni >> 1][(ni & 1) * 2 + 1]);
        }
    }

    const bool wf  = (c.mode & 1) != 0;
    const bool wsp = (c.mode & 2) != 0;
    const bool rel = (c.mode & 4) != 0;
#pragma unroll
    for (int mi = 0; mi < 2; mi++) {
        const int mrow = m0 + wmBase + mi * 16 + (lane >> 2);
#pragma unroll
        for (int ni = 0; ni < 4; ni++) {
            const int n = n0 + wnBase + ni * 8 + (lane & 3) * 2;
#pragma unroll
            for (int half = 0; half < 2; half++) {
                const int mm = mrow + half * 8;
                float v0 = acc[mi][ni][half * 2 + 0];
                float v1 = acc[mi][ni][half * 2 + 1];
                if (n < c.N) v0 += c.bias[n];
                if (n + 1 < c.N) v1 += c.bias[n + 1];
                if (rel) { v0 = fmaxf(v0, 0.f); v1 = fmaxf(v1, 0.f); }
                if (wf) {
                    if (n < c.N)     c.C[(size_t)mm * c.ldc + n]     = v0;
                    if (n + 1 < c.N) c.C[(size_t)mm * c.ldc + n + 1] = v1;
                }
                if (wsp && n + 1 < c.N) {
                    __nv_bfloat16 h0 = __float2bfloat16(v0);
                    __nv_bfloat16 h1 = __float2bfloat16(v1);
                    __nv_bfloat16 l0 = __float2bfloat16(v0 - __bfloat162float(h0));
                    __nv_bfloat16 l1 = __float2bfloat16(v1 - __bfloat162float(h1));
                    __nv_bfloat162 hv; hv.x = h0; hv.y = h1;
                    __nv_bfloat162 lv2; lv2.x = l0; lv2.y = l1;
                    *(__nv_bfloat162*)(c.Cs + (size_t)mm * (2 * c.N) + n) = hv;
                    *(__nv_bfloat162*)(c.Cs + (size_t)mm * (2 * c.N) + c.N + n) = lv2;
                }
            }
        }
    }
}

// ---------------------------------------------------------------- prep kernels
__global__ void split_k(const float* __restrict__ src, __nv_bfloat16* __restrict__ dst,
                        int R, int C) {
    int i = blockIdx.x * blockDim.x + threadIdx.x;
    if (i >= R * C) return;
    int r = i / C, cc = i % C;
    float x = src[i];
    __nv_bfloat16 h = __float2bfloat16(x);
    dst[(size_t)r * 2 * C + cc] = h;
    dst[(size_t)r * 2 * C + C + cc] = __float2bfloat16(x - __bfloat162float(h));
}

__global__ void fuse_w_k(const float* __restrict__ w_ih0, const float* __restrict__ d_fc2w,
                         const float* __restrict__ d_fc2b, const float* __restrict__ b_ih0,
                         float* __restrict__ Wf, float* __restrict__ bfv) {
    __shared__ float w[VV];
    int j = blockIdx.x;
    if (threadIdx.x < VV) w[threadIdx.x] = w_ih0[j * VV + threadIdx.x];
    __syncthreads();
    for (int k = threadIdx.x; k < HH; k += blockDim.x) {
        float s = 0.f;
#pragma unroll
        for (int v = 0; v < VV; v++) s = fmaf(w[v], d_fc2w[v * HH + k], s);
        Wf[(size_t)j * HH + k] = s;
    }
    if (threadIdx.x == 0) {
        float s = b_ih0[j];
#pragma unroll
        for (int v = 0; v < VV; v++) s = fmaf(w[v], d_fc2b[v], s);
        bfv[j] = s;
    }
}

// fused phase-A weight: rows 4j+{0,1,2,3} = {r, z, gi_n, gh_n}; rows 2048+: dfc2
__global__ void build_wa(const float* __restrict__ Wf, const float* __restrict__ whh0,
                         const float* __restrict__ dfc2, __nv_bfloat16* __restrict__ WA) {
    int i = blockIdx.x * blockDim.x + threadIdx.x;
    if (i >= NA * KC) return;
    int r = i >> 10, k = i & 1023;
    float v = 0.f;
    if (r < 2048) {
        int j = r >> 2, g = r & 3;
        if (k < HH) {
            if (g == 0) v = Wf[(size_t)j * HH + k];
            else if (g == 1) v = Wf[(size_t)(512 + j) * HH + k];
            else if (g == 2) v = Wf[(size_t)(1024 + j) * HH + k];
        } else {
            int kk = k - HH;
            if (g == 0) v = whh0[(size_t)j * HH + kk];
            else if (g == 1) v = whh0[(size_t)(512 + j) * HH + kk];
            else if (g == 3) v = whh0[(size_t)(1024 + j) * HH + kk];
        }
    } else {
        int vr = r - 2048;
        if (k < HH) v = dfc2[(size_t)vr * HH + k];
    }
    __nv_bfloat16 hi = __float2bfloat16(v);
    WA[(size_t)r * (2 * KC) + k] = hi;
    WA[(size_t)r * (2 * KC) + KC + k] = __float2bfloat16(v - __bfloat162float(hi));
}

__global__ void build_wb(const float* __restrict__ wih1, const float* __restrict__ whh1,
                         __nv_bfloat16* __restrict__ WB) {
    int i = blockIdx.x * blockDim.x + threadIdx.x;
    if (i >= NB * KC) return;
    int r = i >> 10, k = i & 1023;
    int j = r >> 2, g = r & 3;
    float v = 0.f;
    if (k < HH) {
        if (g == 0) v = wih1[(size_t)j * HH + k];
        else if (g == 1) v = wih1[(size_t)(512 + j) * HH + k];
        else if (g == 2) v = wih1[(size_t)(1024 + j) * HH + k];
    } else {
        int kk = k - HH;
        if (g == 0) v = whh1[(size_t)j * HH + kk];
        else if (g == 1) v = whh1[(size_t)(512 + j) * HH + kk];
        else if (g == 3) v = whh1[(size_t)(1024 + j) * HH + kk];
    }
    __nv_bfloat16 hi = __float2bfloat16(v);
    WB[(size_t)r * (2 * KC) + k] = hi;
    WB[(size_t)r * (2 * KC) + KC + k] = __float2bfloat16(v - __bfloat162float(hi));
}

__global__ void build_bias(const float* __restrict__ bfv, const float* __restrict__ w_ih0,
                           const float* __restrict__ b_ih0, const float* __restrict__ b_hh0,
                           const float* __restrict__ d_fc2b, const float* __restrict__ b_ih1,
                           const float* __restrict__ b_hh1,
                           float* __restrict__ bA0, float* __restrict__ bA1,
                           float* __restrict__ bB) {
    int r = blockIdx.x * blockDim.x + threadIdx.x;
    if (r < NA) {
        if (r < 2048) {
            int j = r >> 2, g = r & 3;
            int idx = (g == 0) ? j : (g == 1) ? 512 + j : 1024 + j;
            float oneh = w_ih0[(size_t)idx * VV + (VV - 1)] + b_ih0[idx];
            float fused = bfv[idx];
            if (g <= 1)      { bA0[r] = oneh + b_hh0[idx]; bA1[r] = fused + b_hh0[idx]; }
            else if (g == 2) { bA0[r] = oneh;              bA1[r] = fused; }
            else             { bA0[r] = b_hh0[idx];        bA1[r] = b_hh0[idx]; }
        } else {
            bA0[r] = bA1[r] = d_fc2b[r - 2048];
        }
    }
    if (r < NB) {
        int j = r >> 2, g = r & 3;
        int idx = (g == 0) ? j : (g == 1) ? 512 + j : 1024 + j;
        if (g <= 1)      bB[r] = b_ih1[idx] + b_hh1[idx];
        else if (g == 2) bB[r] = b_ih1[idx];
        else             bB[r] = b_hh1[idx];
    }
}

__global__ void kld_kernel(const float* __restrict__ mu, const float* __restrict__ lv,
                           float* __restrict__ out) {
    __shared__ float red[1024];
    float s = 0.f;
    for (int i = threadIdx.x; i < BB * ENCD; i += blockDim.x) {
        float m = mu[i], l = lv[i];
        s += 1.f + l - m * m - expf(l);
    }
    red[threadIdx.x] = s;
    __syncthreads();
    for (int off = 512; off > 0; off >>= 1) {
        if (threadIdx.x < off) red[threadIdx.x] += red[threadIdx.x + off];
        __syncthreads();
    }
    if (threadIdx.x == 0) out[0] = -0.5f * red[0] / (float)BB;
}

__global__ void reparam_k(const float* __restrict__ eps, const float* __restrict__ mu,
                          const float* __restrict__ lv, __nv_bfloat16* __restrict__ encs) {
    int i = blockIdx.x * blockDim.x + threadIdx.x;
    if (i >= BB * ENCD) return;
    float v = eps[i] * expf(0.5f * lv[i]) + mu[i];
    int b = i / ENCD, j = i % ENCD;
    __nv_bfloat16 h = __float2bfloat16(v);
    encs[(size_t)b * 2 * ENCD + j] = h;
    encs[(size_t)b * 2 * ENCD + ENCD + j] = __float2bfloat16(v - __bfloat162float(h));
}

// init decoder state: AcatA[0] = [0 | split(h0init)], AcatB[0] h1 slots = 0, h1f = 0
__global__ void init_state(const float* __restrict__ h0f, __nv_bfloat16* __restrict__ AA0,
                           __nv_bfloat16* __restrict__ AB0, float* __restrict__ h1f) {
    int i = blockIdx.x * blockDim.x + threadIdx.x;
    if (i >= BB * HH) return;
    int b = i / HH, j = i % HH;
    float v = h0f[i];
    __nv_bfloat16 hi = __float2bfloat16(v);
    __nv_bfloat16 lo = __float2bfloat16(v - __bfloat162float(hi));
    __nv_bfloat16 z = __float2bfloat16(0.f);
    size_t row = (size_t)b * (2 * KC);
    AA0[row + 512 + j] = hi;
    AA0[row + 1536 + j] = lo;
    AA0[row + j] = z;
    AA0[row + 1024 + j] = z;
    AB0[row + 512 + j] = z;
    AB0[row + 1536 + j] = z;
    h1f[i] = 0.f;
}

// ---------------------------------------------------------------- launcher
#define SMEM64L (3 * (64 + 128) * ROWB)

static inline void launch64(const GemmArgs& a, int nch) {
    int ny = 0;
    for (int i = 0; i < nch; i++) ny += a.ch[i].ntiles;
    gemm_mma64<<<dim3(8, ny), 256, SMEM64L>>>(a);
}

extern "C" void kernel_launch(void* const* d_in, const int* in_sizes, int n_in,
                              void* d_out, int out_size) {
    const float* X       = (const float*)d_in[0];
    const float* eps     = (const float*)d_in[2];
    const float* e_fc1w  = (const float*)d_in[3];
    const float* e_fc1b  = (const float*)d_in[4];
    const float* e_fc2w  = (const float*)d_in[5];
    const float* e_fc2b  = (const float*)d_in[6];
    const float* e_fc3w  = (const float*)d_in[7];
    const float* e_fc3b  = (const float*)d_in[8];
    const float* e_fc41w = (const float*)d_in[9];
    const float* e_fc41b = (const float*)d_in[10];
    const float* e_fc42w = (const float*)d_in[11];
    const float* e_fc42b = (const float*)d_in[12];
    const float* d_fc1w  = (const float*)d_in[13];
    const float* d_fc1b  = (const float*)d_in[14];
    const float* d_fc2w  = (const float*)d_in[15];
    const float* d_fc2b  = (const float*)d_in[16];
    const float* w_ih0   = (const float*)d_in[17];
    const float* b_ih0   = (const float*)d_in[18];
    const float* w_hh0   = (const float*)d_in[19];
    const float* b_hh0   = (const float*)d_in[20];
    const float* w_ih1   = (const float*)d_in[21];
    const float* b_ih1   = (const float*)d_in[22];
    const float* w_hh1   = (const float*)d_in[23];
    const float* b_hh1   = (const float*)d_in[24];

    float* out = (float*)d_out;
    float* kld_out = out + (size_t)BB * SEQL * VV;

    cudaFuncSetAttribute(gemm_mma64, cudaFuncAttributeMaxDynamicSharedMemorySize, SMEM64L);
    cudaFuncSetAttribute(decoder_persist, cudaFuncAttributeMaxDynamicSharedMemorySize,
                         PERSIST_SMEM);

    float* F = nullptr;
    __nv_bfloat16* Sb = nullptr;
    cudaGetSymbolAddress((void**)&F, g_f32);
    cudaGetSymbolAddress((void**)&Sb, g_bf);

    float* mu  = F + F_MU;
    float* lv  = F + F_LV;
    float* h0f = F + F_H0F;
    float* h1f = F + F_H1F;
    float* Wf  = F + F_WF;
    float* bfv = F + F_BFV;
    float* bA0 = F + F_BA0;
    float* bA1 = F + F_BA1;
    float* bB  = F + F_BB2;

    __nv_bfloat16* Xs    = Sb + S_XS;
    __nv_bfloat16* e1ws  = Sb + S_E1WS;
    __nv_bfloat16* h1es  = Sb + S_H1ES;
    __nv_bfloat16* e2ws  = Sb + S_E2WS;
    __nv_bfloat16* h2es  = Sb + S_H2ES;
    __nv_bfloat16* e3ws  = Sb + S_E3WS;
    __nv_bfloat16* h3es  = Sb + S_H3ES;
    __nv_bfloat16* e41s  = Sb + S_E41S;
    __nv_bfloat16* e42s  = Sb + S_E42S;
    __nv_bfloat16* encs  = Sb + S_ENCS;
    __nv_bfloat16* dfc1s = Sb + S_DFC1S;
    __nv_bfloat16* WA    = Sb + S_WA;
    __nv_bfloat16* WB    = Sb + S_WB;
    __nv_bfloat16* AA0   = Sb + S_AA0;
    __nv_bfloat16* AA1   = Sb + S_AA1;
    __nv_bfloat16* AB0   = Sb + S_AB0;
    __nv_bfloat16* AB1   = Sb + S_AB1;

    auto split = [&](const float* s, __nv_bfloat16* d, int R, int C) {
        int n = R * C;
        split_k<<<(n + 255) / 256, 256>>>(s, d, R, C);
    };

    // ---- decoder weight prep ----
    fuse_w_k<<<H3, 256>>>(w_ih0, d_fc2w, d_fc2b, b_ih0, Wf, bfv);
    build_wa<<<(NA * KC + 255) / 256, 256>>>(Wf, w_hh0, d_fc2w, WA);
    build_wb<<<(NB * KC + 255) / 256, 256>>>(w_ih1, w_hh1, WB);
    build_bias<<<(NA + 255) / 256, 256>>>(bfv, w_ih0, b_ih0, b_hh0, d_fc2b,
                                          b_ih1, b_hh1, bA0, bA1, bB);

    // ---- encoder ----
    split(X, Xs, BB, FP);
    split(e_fc1w, e1ws, 2048, FP);
    split(e_fc2w, e2ws, 1024, 2048);
    split(e_fc3w, e3ws, 512, 1024);
    split(e_fc41w, e41s, ENCD, 512);
    split(e_fc42w, e42s, ENCD, 512);
    split(d_fc1w, dfc1s, HH, ENCD);

    {
        GemmArgs a{}; a.K = FP;
        a.ch[0] = {Xs, e1ws, e_fc1b, nullptr, h1es, 2048, 0, 2 | 4, 16};
        launch64(a, 1);
    }
    {
        GemmArgs a{}; a.K = 2048;
        a.ch[0] = {h1es, e2ws, e_fc2b, nullptr, h2es, 1024, 0, 2 | 4, 8};
        launch64(a, 1);
    }
    {
        GemmArgs a{}; a.K = 1024;
        a.ch[0] = {h2es, e3ws, e_fc3b, nullptr, h3es, 512, 0, 2 | 4, 4};
        launch64(a, 1);
    }
    {
        GemmArgs a{}; a.K = 512;
        a.ch[0] = {h3es, e41s, e_fc41b, mu, nullptr, ENCD, ENCD, 1, 1};
        a.ch[1] = {h3es, e42s, e_fc42b, lv, nullptr, ENCD, ENCD, 1, 1};
        launch64(a, 2);
    }
    kld_kernel<<<1, 1024>>>(mu, lv, kld_out);
    reparam_k<<<(BB * ENCD + 255) / 256, 256>>>(eps, mu, lv, encs);
    {
        GemmArgs a{}; a.K = ENCD;
        a.ch[0] = {encs, dfc1s, d_fc1b, h0f, nullptr, HH, HH, 1, 4};
        launch64(a, 1);
    }
    init_state<<<(BB * HH + 255) / 256, 256>>>(h0f, AA0, AB0, h1f);

    // ---- persistent decoder: 128 steps, 2 fused GEMMs/step, grid barriers ----
    PersistArgs p{};
    p.WA = WA; p.WB = WB;
    p.AA0 = AA0; p.AA1 = AA1; p.AB0 = AB0; p.AB1 = AB1;
    p.bA0 = bA0; p.bA1 = bA1; p.bB = bB;
    p.h0f = h0f; p.h1f = h1f;
    p.outp = out;
    decoder_persist<<<GRID_N, 256, PERSIST_SMEM>>>(p);
}

// round 5
// speedup vs baseline: 1.7284x; 1.7284x over previous
#include <cuda_runtime.h>
#include <cuda_bf16.h>
#include <cstdint>

// ---------------------------------------------------------------- dims
#define BB   512
#define FP   4096
#define ENCD 64
#define HH   512
#define VV   42
#define SEQL 128
#define H3   1536

// ---------------------------------------------------------------- fp32 scratch
#define F_MU   0u
#define F_LV   32768u
#define F_H0   65536u
#define F_H1   327680u
#define F_GI0  589824u
#define F_GH0  1376256u
#define F_GI1  2162688u
#define F_GH1  2949120u
#define F_WF   3735552u
#define F_BF   4521984u
#define F_TOTAL 4523520u
__device__ __align__(256) float g_f32[F_TOTAL];

// ---------------------------------------------------------------- bf16 split scratch
#define S_XS     0u
#define S_E1WS   4194304u
#define S_H1ES   20971520u
#define S_E2WS   23068672u
#define S_H2ES   27262976u
#define S_E3WS   28311552u
#define S_H3ES   29360128u
#define S_E41S   29884416u
#define S_E42S   29949952u
#define S_ENCS   30015488u
#define S_DFC1S  30081024u
#define S_H0S    30146560u
#define S_H1S    30670848u
#define S_WFS    31195136u
#define S_WHH0S  32768000u
#define S_WHH1S  34340864u
#define S_WIH1S  35913728u
#define S_DFC2S  37486592u
#define S_TOTAL  37529600u
__device__ __align__(256) __nv_bfloat16 g_bf[S_TOTAL];

// ---------------------------------------------------------------- PTX helpers
__device__ __forceinline__ uint32_t smem_u32(const void* p) {
    uint32_t a;
    asm("{ .reg .u64 t; cvta.to.shared.u64 t, %1; cvt.u32.u64 %0, t; }" : "=r"(a) : "l"(p));
    return a;
}
__device__ __forceinline__ void cp16(uint32_t dst, const void* src) {
    asm volatile("cp.async.cg.shared.global [%0], [%1], 16;\n" :: "r"(dst), "l"(src));
}
__device__ __forceinline__ void cp16z(uint32_t dst, const void* src, int sz) {
    asm volatile("cp.async.cg.shared.global [%0], [%1], 16, %2;\n"
                 :: "r"(dst), "l"(src), "r"(sz));
}
__device__ __forceinline__ void ldm4(uint32_t* r, uint32_t addr) {
    asm volatile("ldmatrix.sync.aligned.m8n8.x4.shared.b16 {%0,%1,%2,%3}, [%4];\n"
                 : "=r"(r[0]), "=r"(r[1]), "=r"(r[2]), "=r"(r[3]) : "r"(addr));
}
__device__ __forceinline__ void mma16816(float* c, const uint32_t* a, uint32_t b0, uint32_t b1) {
    asm volatile(
        "mma.sync.aligned.m16n8k16.row.col.f32.bf16.bf16.f32 "
        "{%0,%1,%2,%3}, {%4,%5,%6,%7}, {%8,%9}, {%0,%1,%2,%3};\n"
        : "+f"(c[0]), "+f"(c[1]), "+f"(c[2]), "+f"(c[3])
        : "r"(a[0]), "r"(a[1]), "r"(a[2]), "r"(a[3]), "r"(b0), "r"(b1));
}

// ---------------------------------------------------------------- GEMM (bf16x3)
// C[m,n] = act( sum_k Afp32[m,k] * Wfp32[n,k] + bias[n] )
// A, W stored as bf16 split [rows, 2K] = [hi | lo].  K' = 3K via segments:
//   seg0: Ah*Wh   seg1: Al*Wh   seg2: Ah*Wl
struct Chunk {
    const __nv_bfloat16* A;
    const __nv_bfloat16* W;
    const float* bias;
    float* C;
    __nv_bfloat16* Cs;
    int N;
    int ldc;
    int mode;   // 1=fp32 out, 2=split out, 4=relu
    int ntiles; // ceil(N/128)
};
struct GemmArgs {
    Chunk ch[4];
    int K;
};

#define ROWB 80   // padded smem row: 32 bf16 (64B) + 16B pad
#define NSTAGE 4

template <int BM>
__global__ void __launch_bounds__(512) gemm_mma(GemmArgs args) {
    constexpr int STB = (BM + 128) * ROWB;
    constexpr int MI = BM / 64;          // m16 frags per warp (warp m-tile = BM/4)
    extern __shared__ __align__(128) char smbuf[];
    const uint32_t sb = smem_u32(smbuf);
    const int tid = threadIdx.x;
    const int lane = tid & 31, wid = tid >> 5;
    const int wmBase = (wid >> 2) * (BM / 4);
    const int wnBase = (wid & 3) * 32;

    int rem = blockIdx.y, ci = 0;
    while (rem >= args.ch[ci].ntiles) { rem -= args.ch[ci].ntiles; ci++; }
    const Chunk c = args.ch[ci];
    const int n0 = rem * 128;
    const int m0 = blockIdx.x * BM;
    const int K = args.K;
    const int ksub = K >> 5;
    const int Kt = 3 * ksub;
    const int ld2 = 2 * K;

    auto issue = [&](int kt) {
        const int seg = (kt >= 2 * ksub) ? 2 : (kt >= ksub) ? 1 : 0;
        const int kk = kt - seg * ksub;
        const int aCol = kk * 32 + (seg == 1 ? K : 0);
        const int bCol = kk * 32 + (seg == 2 ? K : 0);
        const uint32_t sA = sb + (kt & 3) * STB;
        const uint32_t sB = sA + BM * ROWB;
        const int row = tid >> 2, ch = tid & 3;
        if (BM == 128 || tid < 256) {
            cp16(sA + row * ROWB + ch * 16,
                 c.A + (size_t)(m0 + row) * ld2 + aCol + ch * 8);
        }
        {
            int n = n0 + row;
            int ok = (n < c.N);
            cp16z(sB + row * ROWB + ch * 16,
                  c.W + (size_t)(ok ? n : 0) * ld2 + bCol + ch * 8, ok ? 16 : 0);
        }
        asm volatile("cp.async.commit_group;\n" ::: "memory");
    };

    float acc[MI][4][4];
#pragma unroll
    for (int mi = 0; mi < MI; mi++)
#pragma unroll
        for (int ni = 0; ni < 4; ni++)
#pragma unroll
            for (int q = 0; q < 4; q++) acc[mi][ni][q] = 0.f;

    issue(0); issue(1); issue(2);

    for (int kt = 0; kt < Kt; kt++) {
        asm volatile("cp.async.wait_group 2;\n" ::: "memory");
        __syncthreads();
        if (kt + 3 < Kt) issue(kt + 3);

        const uint32_t sA = sb + (kt & 3) * STB;
        const uint32_t sB = sA + BM * ROWB;
#pragma unroll
        for (int kh = 0; kh < 2; kh++) {
            uint32_t a[MI][4], b[2][4];
#pragma unroll
            for (int mi = 0; mi < MI; mi++) {
                uint32_t addr = sA + (wmBase + mi * 16 + (lane & 15)) * ROWB
                              + kh * 32 + ((lane >> 4) * 16);
                ldm4(a[mi], addr);
            }
#pragma unroll
            for (int nj = 0; nj < 2; nj++) {
                int grp = lane >> 3;
                int nrow = wnBase + nj * 16 + ((grp >> 1) * 8) + (lane & 7);
                uint32_t addr = sB + nrow * ROWB + (kh * 16 + (grp & 1) * 8) * 2;
                ldm4(b[nj], addr);
            }
#pragma unroll
            for (int mi = 0; mi < MI; mi++)
#pragma unroll
                for (int ni = 0; ni < 4; ni++)
                    mma16816(acc[mi][ni], a[mi],
                             b[ni >> 1][(ni & 1) * 2], b[ni >> 1][(ni & 1) * 2 + 1]);
        }
    }

    // ---------------- epilogue ----------------
    const bool wf  = (c.mode & 1) != 0;
    const bool wsp = (c.mode & 2) != 0;
    const bool rel = (c.mode & 4) != 0;
#pragma unroll
    for (int mi = 0; mi < MI; mi++) {
        const int mrow = m0 + wmBase + mi * 16 + (lane >> 2);
#pragma unroll
        for (int ni = 0; ni < 4; ni++) {
            const int n = n0 + wnBase + ni * 8 + (lane & 3) * 2;
#pragma unroll
            for (int half = 0; half < 2; half++) {
                const int mm = mrow + half * 8;
                float v0 = acc[mi][ni][half * 2 + 0];
                float v1 = acc[mi][ni][half * 2 + 1];
                if (n < c.N) v0 += c.bias[n];
                if (n + 1 < c.N) v1 += c.bias[n + 1];
                if (rel) { v0 = fmaxf(v0, 0.f); v1 = fmaxf(v1, 0.f); }
                if (wf) {
                    if (n < c.N)     c.C[(size_t)mm * c.ldc + n]     = v0;
                    if (n + 1 < c.N) c.C[(size_t)mm * c.ldc + n + 1] = v1;
                }
                if (wsp && n + 1 < c.N) {
                    __nv_bfloat16 h0 = __float2bfloat16(v0);
                    __nv_bfloat16 h1 = __float2bfloat16(v1);
                    __nv_bfloat16 l0 = __float2bfloat16(v0 - __bfloat162float(h0));
                    __nv_bfloat16 l1 = __float2bfloat16(v1 - __bfloat162float(h1));
                    __nv_bfloat162 hv; hv.x = h0; hv.y = h1;
                    __nv_bfloat162 lv2; lv2.x = l0; lv2.y = l1;
                    *(__nv_bfloat162*)(c.Cs + (size_t)mm * (2 * c.N) + n) = hv;
                    *(__nv_bfloat162*)(c.Cs + (size_t)mm * (2 * c.N) + c.N + n) = lv2;
                }
            }
        }
    }
}

// ---------------------------------------------------------------- small kernels
__device__ __forceinline__ float sigf(float x) { return 1.f / (1.f + expf(-x)); }

__global__ void split_k(const float* __restrict__ src, __nv_bfloat16* __restrict__ dst,
                        int R, int C) {
    int i = blockIdx.x * blockDim.x + threadIdx.x;
    if (i >= R * C) return;
    int r = i / C, cc = i % C;
    float x = src[i];
    __nv_bfloat16 h = __float2bfloat16(x);
    dst[(size_t)r * 2 * C + cc] = h;
    dst[(size_t)r * 2 * C + C + cc] = __float2bfloat16(x - __bfloat162float(h));
}

__global__ void gru_combine(const float* __restrict__ gi, const float* __restrict__ gh,
                            float* __restrict__ h, __nv_bfloat16* __restrict__ hs) {
    int idx = blockIdx.x * blockDim.x + threadIdx.x;
    if (idx >= BB * HH) return;
    int b = idx / HH, j = idx % HH;
    const float* gib = gi + (size_t)b * H3;
    const float* ghb = gh + (size_t)b * H3;
    float r = sigf(gib[j] + ghb[j]);
    float z = sigf(gib[j + HH] + ghb[j + HH]);
    float n = tanhf(gib[j + 2 * HH] + r * ghb[j + 2 * HH]);
    float v = (1.f - z) * n + z * h[idx];
    h[idx] = v;
    __nv_bfloat16 hi = __float2bfloat16(v);
    hs[(size_t)b * 2 * HH + j] = hi;
    hs[(size_t)b * 2 * HH + HH + j] = __float2bfloat16(v - __bfloat162float(hi));
}

__global__ void fill_gi0_k(const float* __restrict__ w_ih0, const float* __restrict__ b_ih0,
                           float* __restrict__ gi0) {
    int idx = blockIdx.x * blockDim.x + threadIdx.x;
    if (idx >= BB * H3) return;
    int j = idx % H3;
    gi0[idx] = w_ih0[j * VV + (VV - 1)] + b_ih0[j];  // one-hot at index 41
}

__global__ void fuse_w_k(const float* __restrict__ w_ih0, const float* __restrict__ d_fc2w,
                         const float* __restrict__ d_fc2b, const float* __restrict__ b_ih0,
                         float* __restrict__ Wf, float* __restrict__ bf) {
    __shared__ float w[VV];
    int j = blockIdx.x;
    if (threadIdx.x < VV) w[threadIdx.x] = w_ih0[j * VV + threadIdx.x];
    __syncthreads();
    for (int k = threadIdx.x; k < HH; k += blockDim.x) {
        float s = 0.f;
#pragma unroll
        for (int v = 0; v < VV; v++) s = fmaf(w[v], d_fc2w[v * HH + k], s);
        Wf[(size_t)j * HH + k] = s;
    }
    if (threadIdx.x == 0) {
        float s = b_ih0[j];
#pragma unroll
        for (int v = 0; v < VV; v++) s = fmaf(w[v], d_fc2b[v], s);
        bf[j] = s;
    }
}

__global__ void kld_kernel(const float* __restrict__ mu, const float* __restrict__ lv,
                           float* __restrict__ out) {
    __shared__ float red[1024];
    float s = 0.f;
    for (int i = threadIdx.x; i < BB * ENCD; i += blockDim.x) {
        float m = mu[i], l = lv[i];
        s += 1.f + l - m * m - expf(l);
    }
    red[threadIdx.x] = s;
    __syncthreads();
    for (int off = 512; off > 0; off >>= 1) {
        if (threadIdx.x < off) red[threadIdx.x] += red[threadIdx.x + off];
        __syncthreads();
    }
    if (threadIdx.x == 0) out[0] = -0.5f * red[0] / (float)BB;
}

__global__ void reparam_k(const float* __restrict__ eps, const float* __restrict__ mu,
                          const float* __restrict__ lv, __nv_bfloat16* __restrict__ encs) {
    int i = blockIdx.x * blockDim.x + threadIdx.x;
    if (i >= BB * ENCD) return;
    float v = eps[i] * expf(0.5f * lv[i]) + mu[i];
    int b = i / ENCD, j = i % ENCD;
    __nv_bfloat16 h = __float2bfloat16(v);
    encs[(size_t)b * 2 * ENCD + j] = h;
    encs[(size_t)b * 2 * ENCD + ENCD + j] = __float2bfloat16(v - __bfloat162float(h));
}

__global__ void init_h1_k(float* __restrict__ h1, __nv_bfloat16* __restrict__ h1s) {
    int i = blockIdx.x * blockDim.x + threadIdx.x;
    if (i < BB * HH) h1[i] = 0.f;
    if (i < BB * 2 * HH) h1s[i] = __float2bfloat16(0.f);
}

// ---------------------------------------------------------------- launcher
#define SMEM128 (NSTAGE * (128 + 128) * ROWB)   // 81920
#define SMEM64  (NSTAGE * (64 + 128) * ROWB)    // 61440

static inline void launch128(const GemmArgs& a, int nch) {
    int ny = 0;
    for (int i = 0; i < nch; i++) ny += a.ch[i].ntiles;
    gemm_mma<128><<<dim3(4, ny), 512, SMEM128>>>(a);
}
static inline void launch64(const GemmArgs& a, int nch) {
    int ny = 0;
    for (int i = 0; i < nch; i++) ny += a.ch[i].ntiles;
    gemm_mma<64><<<dim3(8, ny), 512, SMEM64>>>(a);
}

extern "C" void kernel_launch(void* const* d_in, const int* in_sizes, int n_in,
                              void* d_out, int out_size) {
    const float* X       = (const float*)d_in[0];
    const float* eps     = (const float*)d_in[2];
    const float* e_fc1w  = (const float*)d_in[3];
    const float* e_fc1b  = (const float*)d_in[4];
    const float* e_fc2w  = (const float*)d_in[5];
    const float* e_fc2b  = (const float*)d_in[6];
    const float* e_fc3w  = (const float*)d_in[7];
    const float* e_fc3b  = (const float*)d_in[8];
    const float* e_fc41w = (const float*)d_in[9];
    const float* e_fc41b = (const float*)d_in[10];
    const float* e_fc42w = (const float*)d_in[11];
    const float* e_fc42b = (const float*)d_in[12];
    const float* d_fc1w  = (const float*)d_in[13];
    const float* d_fc1b  = (const float*)d_in[14];
    const float* d_fc2w  = (const float*)d_in[15];
    const float* d_fc2b  = (const float*)d_in[16];
    const float* w_ih0   = (const float*)d_in[17];
    const float* b_ih0   = (const float*)d_in[18];
    const float* w_hh0   = (const float*)d_in[19];
    const float* b_hh0   = (const float*)d_in[20];
    const float* w_ih1   = (const float*)d_in[21];
    const float* b_ih1   = (const float*)d_in[22];
    const float* w_hh1   = (const float*)d_in[23];
    const float* b_hh1   = (const float*)d_in[24];

    float* out = (float*)d_out;
    float* kld_out = out + (size_t)BB * SEQL * VV;

    cudaFuncSetAttribute(gemm_mma<128>, cudaFuncAttributeMaxDynamicSharedMemorySize, SMEM128);
    cudaFuncSetAttribute(gemm_mma<64>,  cudaFuncAttributeMaxDynamicSharedMemorySize, SMEM64);

    float* F = nullptr;
    __nv_bfloat16* Sb = nullptr;
    cudaGetSymbolAddress((void**)&F, g_f32);
    cudaGetSymbolAddress((void**)&Sb, g_bf);

    float* mu  = F + F_MU;
    float* lv  = F + F_LV;
    float* h0  = F + F_H0;
    float* h1  = F + F_H1;
    float* gi0 = F + F_GI0;
    float* gh0 = F + F_GH0;
    float* gi1 = F + F_GI1;
    float* gh1 = F + F_GH1;
    float* Wf  = F + F_WF;
    float* bf  = F + F_BF;

    __nv_bfloat16* Xs    = Sb + S_XS;
    __nv_bfloat16* e1ws  = Sb + S_E1WS;
    __nv_bfloat16* h1es  = Sb + S_H1ES;
    __nv_bfloat16* e2ws  = Sb + S_E2WS;
    __nv_bfloat16* h2es  = Sb + S_H2ES;
    __nv_bfloat16* e3ws  = Sb + S_E3WS;
    __nv_bfloat16* h3es  = Sb + S_H3ES;
    __nv_bfloat16* e41s  = Sb + S_E41S;
    __nv_bfloat16* e42s  = Sb + S_E42S;
    __nv_bfloat16* encs  = Sb + S_ENCS;
    __nv_bfloat16* dfc1s = Sb + S_DFC1S;
    __nv_bfloat16* h0s   = Sb + S_H0S;
    __nv_bfloat16* h1s   = Sb + S_H1S;
    __nv_bfloat16* wfs   = Sb + S_WFS;
    __nv_bfloat16* whh0s = Sb + S_WHH0S;
    __nv_bfloat16* whh1s = Sb + S_WHH1S;
    __nv_bfloat16* wih1s = Sb + S_WIH1S;
    __nv_bfloat16* dfc2s = Sb + S_DFC2S;

    auto split = [&](const float* s, __nv_bfloat16* d, int R, int C) {
        int n = R * C;
        split_k<<<(n + 255) / 256, 256>>>(s, d, R, C);
    };

    // one-time splits (per launch)
    split(X, Xs, BB, FP);
    split(e_fc1w, e1ws, 2048, FP);
    split(e_fc2w, e2ws, 1024, 2048);
    split(e_fc3w, e3ws, 512, 1024);
    split(e_fc41w, e41s, ENCD, 512);
    split(e_fc42w, e42s, ENCD, 512);
    split(d_fc1w, dfc1s, HH, ENCD);
    split(d_fc2w, dfc2s, VV, HH);
    split(w_hh0, whh0s, H3, HH);
    split(w_hh1, whh1s, H3, HH);
    split(w_ih1, wih1s, H3, HH);
    fuse_w_k<<<H3, 256>>>(w_ih0, d_fc2w, d_fc2b, b_ih0, Wf, bf);
    split(Wf, wfs, H3, HH);

    // --- encoder ---
    {
        GemmArgs a{}; a.K = FP;
        a.ch[0] = {Xs, e1ws, e_fc1b, nullptr, h1es, 2048, 0, 2 | 4, 16};
        launch64(a, 1);
    }
    {
        GemmArgs a{}; a.K = 2048;
        a.ch[0] = {h1es, e2ws, e_fc2b, nullptr, h2es, 1024, 0, 2 | 4, 8};
        launch64(a, 1);
    }
    {
        GemmArgs a{}; a.K = 1024;
        a.ch[0] = {h2es, e3ws, e_fc3b, nullptr, h3es, 512, 0, 2 | 4, 4};
        launch64(a, 1);
    }
    {
        GemmArgs a{}; a.K = 512;
        a.ch[0] = {h3es, e41s, e_fc41b, mu, nullptr, ENCD, ENCD, 1, 1};
        a.ch[1] = {h3es, e42s, e_fc42b, lv, nullptr, ENCD, ENCD, 1, 1};
        launch64(a, 2);
    }
    kld_kernel<<<1, 1024>>>(mu, lv, kld_out);
    reparam_k<<<(BB * ENCD + 255) / 256, 256>>>(eps, mu, lv, encs);
    {
        GemmArgs a{}; a.K = ENCD;
        a.ch[0] = {encs, dfc1s, d_fc1b, h0, h0s, HH, HH, 1 | 2, 4};
        launch64(a, 1);
    }
    init_h1_k<<<(BB * 2 * HH + 255) / 256, 256>>>(h1, h1s);
    fill_gi0_k<<<(BB * H3 + 255) / 256, 256>>>(w_ih0, b_ih0, gi0);

    // --- GRU decoder ---
    for (int t = 0; t < SEQL; t++) {
        GemmArgs a{}; a.K = HH;
        int nch;
        if (t == 0) {
            a.ch[0] = {h0s, whh0s, b_hh0, gh0, nullptr, H3, H3, 1, 12};
            a.ch[1] = {h1s, whh1s, b_hh1, gh1, nullptr, H3, H3, 1, 12};
            nch = 2;
        } else {
            a.ch[0] = {h1s, wfs,   bf,    gi0, nullptr, H3, H3, 1, 12};
            a.ch[1] = {h0s, whh0s, b_hh0, gh0, nullptr, H3, H3, 1, 12};
            a.ch[2] = {h1s, whh1s, b_hh1, gh1, nullptr, H3, H3, 1, 12};
            a.ch[3] = {h1s, dfc2s, d_fc2b, out + (size_t)(t - 1) * VV, nullptr,
                       VV, SEQL * VV, 1, 1};
            nch = 4;
        }
        launch128(a, nch);

        gru_combine<<<(BB * HH + 255) / 256, 256>>>(gi0, gh0, h0, h0s);

        GemmArgs b{}; b.K = HH;
        b.ch[0] = {h0s, wih1s, b_ih1, gi1, nullptr, H3, H3, 1, 12};
        launch64(b, 1);

        gru_combine<<<(BB * HH + 255) / 256, 256>>>(gi1, gh1, h1, h1s);
    }

    {
        GemmArgs a{}; a.K = HH;
        a.ch[0] = {h1s, dfc2s, d_fc2b, out + (size_t)(SEQL - 1) * VV, nullptr,
                   VV, SEQL * VV, 1, 1};
        launch128(a, 1);
    }
}

// round 6
// speedup vs baseline: 1.7757x; 1.0274x over previous
#include <cuda_runtime.h>
#include <cuda_bf16.h>
#include <cstdint>

// ---------------------------------------------------------------- dims
#define BB   512
#define FP   4096
#define ENCD 64
#define HH   512
#define VV   42
#define SEQL 128
#define H3   1536
#define GRID_N 148

// ---------------------------------------------------------------- fp32 scratch (floats)
#define F_MU    0u
#define F_LV    32768u
#define F_H0F   65536u
#define F_H1F   327680u
#define F_WFP   589824u      // Wf [1536,512]
#define F_BF    1376256u     // bf [1536]
#define F_BRZ0  1377792u     // [1024]
#define F_BRZ   1378816u
#define F_BGIN0 1379840u     // [512]
#define F_BGIN  1380352u
#define F_BGHN  1380864u
#define F_RZP0  1381376u     // [512,1024]
#define F_RZP1  1905664u
#define F_GI0N  2429952u     // [512,512]
#define F_GH0N  2692096u
#define F_GH1   2954240u     // [512,1536]
#define F_GI1P0 3740672u
#define F_GI1P1 4527104u
#define F_TOTAL 5313536u
__device__ __align__(256) float g_f32[F_TOTAL];

// ---------------------------------------------------------------- bf16 scratch (elems)
#define S_XS     0u
#define S_E1WS   4194304u
#define S_H1ES   20971520u
#define S_E2WS   23068672u
#define S_H2ES   27262976u
#define S_E3WS   28311552u
#define S_H3ES   29360128u
#define S_E41S   29884416u
#define S_E42S   29949952u
#define S_ENCS   30015488u
#define S_DFC1S  30081024u
#define S_ACAT   30146560u   // [512, 2048] : hi[h1|h0] , lo[h1|h0]
#define S_WRZ    31195136u   // [1024, 2048]
#define S_WFN    33292288u   // [512, 1024]
#define S_WH0N   33816576u   // [512, 1024]
#define S_WGH1   34340864u   // [1536, 1024]
#define S_WIH1   35913728u   // [1536, 1024]
#define S_WOUT   37486592u   // [42, 1024]
#define S_TOTAL  37529600u
__device__ __align__(256) __nv_bfloat16 g_bf[S_TOTAL];

__device__ int g_bar_cnt;
__device__ volatile unsigned g_bar_gen;

// ---------------------------------------------------------------- PTX helpers
__device__ __forceinline__ uint32_t smem_u32(const void* p) {
    uint32_t a;
    asm("{ .reg .u64 t; cvta.to.shared.u64 t, %1; cvt.u32.u64 %0, t; }" : "=r"(a) : "l"(p));
    return a;
}
__device__ __forceinline__ void cp16(uint32_t dst, const void* src) {
    asm volatile("cp.async.cg.shared.global [%0], [%1], 16;\n" :: "r"(dst), "l"(src));
}
__device__ __forceinline__ void cp16z(uint32_t dst, const void* src, int sz) {
    asm volatile("cp.async.cg.shared.global [%0], [%1], 16, %2;\n"
                 :: "r"(dst), "l"(src), "r"(sz));
}
__device__ __forceinline__ void ldm4(uint32_t* r, uint32_t addr) {
    asm volatile("ldmatrix.sync.aligned.m8n8.x4.shared.b16 {%0,%1,%2,%3}, [%4];\n"
                 : "=r"(r[0]), "=r"(r[1]), "=r"(r[2]), "=r"(r[3]) : "r"(addr));
}
__device__ __forceinline__ void mma16816(float* c, const uint32_t* a, uint32_t b0, uint32_t b1) {
    asm volatile(
        "mma.sync.aligned.m16n8k16.row.col.f32.bf16.bf16.f32 "
        "{%0,%1,%2,%3}, {%4,%5,%6,%7}, {%8,%9}, {%0,%1,%2,%3};\n"
        : "+f"(c[0]), "+f"(c[1]), "+f"(c[2]), "+f"(c[3])
        : "r"(a[0]), "r"(a[1]), "r"(a[2]), "r"(a[3]), "r"(b0), "r"(b1));
}
__device__ __forceinline__ float sigf(float x) { return 1.f / (1.f + expf(-x)); }
__device__ __forceinline__ float ldcg(const float* p) {
    float v;
    asm volatile("ld.global.cg.f32 %0, [%1];" : "=f"(v) : "l"(p));
    return v;
}

#define ROWB 80
#define STBP ((128 + 128) * ROWB)
#define PERSIST_SMEM (4 * STBP)   // 81920

// ---------------------------------------------------------------- grid barrier
__device__ __forceinline__ void grid_bar() {
    __syncthreads();
    if (threadIdx.x == 0) {
        unsigned gen = g_bar_gen;
        __threadfence();
        if (atomicAdd(&g_bar_cnt, 1) == GRID_N - 1) {
            atomicExch(&g_bar_cnt, 0);
            __threadfence();
            g_bar_gen = gen + 1;
        } else {
            while (g_bar_gen == gen) { __nanosleep(32); }
            __threadfence();
        }
    }
    __syncthreads();
}

// ---------------------------------------------------------------- persistent GEMM tile
// C[m,n] = sum over k-range of Afp32[m,k]*Wfp32[n,k] via bf16x3.
// A = Acat [512, 2048] (hi cols [0,1024), lo [1024,2048)); aHi selects slot.
// W [rows, ldW]: hi cols [wHi+k], lo at +wLoD.
__device__ void gemm_tile_p(const __nv_bfloat16* __restrict__ A,
                            const __nv_bfloat16* __restrict__ W,
                            int ldW, int wLoD, int aHi, int wHi, int k0, int ksub,
                            int m0, int n0, int nValid,
                            uint32_t sb, int tid, float acc[2][4][4]) {
    const int lane = tid & 31, wid = tid >> 5;
    const int wmBase = (wid >> 2) * 32;
    const int wnBase = (wid & 3) * 32;
    const int Kt = 3 * ksub;

#pragma unroll
    for (int mi = 0; mi < 2; mi++)
#pragma unroll
        for (int ni = 0; ni < 4; ni++)
#pragma unroll
            for (int q = 0; q < 4; q++) acc[mi][ni][q] = 0.f;

    auto issue = [&](int kt) {
        const int seg = (kt >= 2 * ksub) ? 2 : (kt >= ksub) ? 1 : 0;
        const int kk = kt - seg * ksub;
        const int aCol = aHi + k0 + kk * 32 + (seg == 1 ? 1024 : 0);
        const int wCol = wHi + k0 + kk * 32 + (seg == 2 ? wLoD : 0);
        const uint32_t sA = sb + (kt & 3) * STBP;
        const uint32_t sB = sA + 128 * ROWB;
        const int row = tid >> 2, ch = tid & 3;
        cp16(sA + row * ROWB + ch * 16,
             A + (size_t)(m0 + row) * 2048 + aCol + ch * 8);
        int n = n0 + row;
        int ok = (n < nValid);
        cp16z(sB + row * ROWB + ch * 16,
              W + (size_t)(ok ? n : 0) * ldW + wCol + ch * 8, ok ? 16 : 0);
        asm volatile("cp.async.commit_group;\n" ::: "memory");
    };

    issue(0); issue(1); issue(2);
    for (int kt = 0; kt < Kt; kt++) {
        asm volatile("cp.async.wait_group 2;\n" ::: "memory");
        __syncthreads();
        if (kt + 3 < Kt) issue(kt + 3);
        else asm volatile("cp.async.commit_group;\n" ::: "memory");

        const uint32_t sA = sb + (kt & 3) * STBP;
        const uint32_t sB = sA + 128 * ROWB;
#pragma unroll
        for (int kh = 0; kh < 2; kh++) {
            uint32_t a[2][4], b[2][4];
#pragma unroll
            for (int mi = 0; mi < 2; mi++) {
                uint32_t addr = sA + (wmBase + mi * 16 + (lane & 15)) * ROWB
                              + kh * 32 + ((lane >> 4) * 16);
                ldm4(a[mi], addr);
            }
#pragma unroll
            for (int nj = 0; nj < 2; nj++) {
                int grp = lane >> 3;
                int nrow = wnBase + nj * 16 + ((grp >> 1) * 8) + (lane & 7);
                uint32_t addr = sB + nrow * ROWB + (kh * 16 + (grp & 1) * 8) * 2;
                ldm4(b[nj], addr);
            }
#pragma unroll
            for (int mi = 0; mi < 2; mi++)
#pragma unroll
                for (int ni = 0; ni < 4; ni++)
                    mma16816(acc[mi][ni], a[mi],
                             b[ni >> 1][(ni & 1) * 2], b[ni >> 1][(ni & 1) * 2 + 1]);
        }
    }
    __syncthreads();
}

__device__ void epi_raw(float acc[2][4][4], float* __restrict__ C, int cld,
                        int m0, int n0, int nValid, int tid) {
    const int lane = tid & 31, wid = tid >> 5;
    const int wmBase = (wid >> 2) * 32;
    const int wnBase = (wid & 3) * 32;
#pragma unroll
    for (int mi = 0; mi < 2; mi++) {
        const int mrow = m0 + wmBase + mi * 16 + (lane >> 2);
#pragma unroll
        for (int ni = 0; ni < 4; ni++) {
            const int n = n0 + wnBase + ni * 8 + (lane & 3) * 2;
#pragma unroll
            for (int half = 0; half < 2; half++) {
                const int mm = mrow + half * 8;
                if (n < nValid)     C[(size_t)mm * cld + n]     = acc[mi][ni][half * 2];
                if (n + 1 < nValid) C[(size_t)mm * cld + n + 1] = acc[mi][ni][half * 2 + 1];
            }
        }
    }
}

__device__ void epi_out_p(float acc[2][4][4], const float* __restrict__ biasO,
                          int m0, float* __restrict__ outp, int tOut, int tid) {
    const int lane = tid & 31, wid = tid >> 5;
    const int wmBase = (wid >> 2) * 32;
    const int wnBase = (wid & 3) * 32;
#pragma unroll
    for (int mi = 0; mi < 2; mi++) {
#pragma unroll
        for (int ni = 0; ni < 4; ni++) {
            const int v = wnBase + ni * 8 + (lane & 3) * 2;
#pragma unroll
            for (int half = 0; half < 2; half++) {
                const int mm = m0 + wmBase + mi * 16 + (lane >> 2) + half * 8;
                if (v < VV)
                    outp[(size_t)mm * (SEQL * VV) + tOut * VV + v] =
                        acc[mi][ni][half * 2] + biasO[v];
                if (v + 1 < VV)
                    outp[(size_t)mm * (SEQL * VV) + tOut * VV + v + 1] =
                        acc[mi][ni][half * 2 + 1] + biasO[v + 1];
            }
        }
    }
}

// ---------------------------------------------------------------- persistent decoder
struct DP {
    __nv_bfloat16* ACAT;
    const __nv_bfloat16 *WRZ, *WFN, *WH0N, *WGH1, *WIH1, *WOUT;
    float *RZP0, *RZP1, *GI0N, *GH0N, *GH1, *GI1P0, *GI1P1;
    const float *brz0, *brz, *bgin0, *bgin, *bghn, *bih1, *bhh1, *dfc2b;
    float *h0f, *h1f, *outp;
};

__device__ __forceinline__ void combine0_dev(const DP& p, int t, int gid) {
    for (int i = gid; i < BB * HH; i += GRID_N * 512) {
        const int m = i >> 9, j = i & 511;
        float rp = ldcg(p.RZP0 + m * 1024 + j) + ldcg(p.RZP1 + m * 1024 + j)
                 + (t == 0 ? p.brz0[j] : p.brz[j]);
        float zp = ldcg(p.RZP0 + m * 1024 + 512 + j) + ldcg(p.RZP1 + m * 1024 + 512 + j)
                 + (t == 0 ? p.brz0[512 + j] : p.brz[512 + j]);
        float gin = ldcg(p.GI0N + i) + (t == 0 ? p.bgin0[j] : p.bgin[j]);
        float ghn = ldcg(p.GH0N + i) + p.bghn[j];
        float r = sigf(rp), z = sigf(zp);
        float nv = tanhf(gin + r * ghn);
        float h = (1.f - z) * nv + z * p.h0f[i];
        p.h0f[i] = h;
        __nv_bfloat16 hi = __float2bfloat16(h);
        __nv_bfloat16 lo = __float2bfloat16(h - __bfloat162float(hi));
        p.ACAT[(size_t)m * 2048 + 512 + j] = hi;
        p.ACAT[(size_t)m * 2048 + 1536 + j] = lo;
    }
}

__device__ __forceinline__ void combine1_dev(const DP& p, int gid) {
    for (int i = gid; i < BB * HH; i += GRID_N * 512) {
        const int m = i >> 9, j = i & 511;
        const size_t r0 = (size_t)m * 1536;
        float rp = ldcg(p.GI1P0 + r0 + j) + ldcg(p.GI1P1 + r0 + j) + p.bih1[j]
                 + ldcg(p.GH1 + r0 + j) + p.bhh1[j];
        float zp = ldcg(p.GI1P0 + r0 + 512 + j) + ldcg(p.GI1P1 + r0 + 512 + j)
                 + p.bih1[512 + j] + ldcg(p.GH1 + r0 + 512 + j) + p.bhh1[512 + j];
        float gin = ldcg(p.GI1P0 + r0 + 1024 + j) + ldcg(p.GI1P1 + r0 + 1024 + j)
                  + p.bih1[1024 + j];
        float ghn = ldcg(p.GH1 + r0 + 1024 + j) + p.bhh1[1024 + j];
        float r = sigf(rp), z = sigf(zp);
        float nv = tanhf(gin + r * ghn);
        float h = (1.f - z) * nv + z * p.h1f[i];
        p.h1f[i] = h;
        __nv_bfloat16 hi = __float2bfloat16(h);
        __nv_bfloat16 lo = __float2bfloat16(h - __bfloat162float(hi));
        p.ACAT[(size_t)m * 2048 + j] = hi;
        p.ACAT[(size_t)m * 2048 + 1024 + j] = lo;
    }
}

__global__ void __launch_bounds__(512, 1) decoder_persist(DP p) {
    extern __shared__ __align__(128) char smbuf[];
    const uint32_t sb = smem_u32(smbuf);
    const int tid = threadIdx.x;
    const int cid = blockIdx.x;
    const int gid = cid * 512 + tid;
    float acc[2][4][4];

    // ---- phase-A tile descriptor ----
    const __nv_bfloat16* Wd;
    float* Cd = nullptr;
    int ldW, wLoD, aHi, wHi, n0, nValid, m0, cld;
    bool isOut = false;
    if (cid < 64) {
        int m = cid & 3, rest = cid >> 2;
        int nt = rest & 7, half = rest >> 3;
        Wd = p.WRZ; ldW = 2048; wLoD = 1024;
        wHi = half * 512; aHi = half * 512;
        m0 = m * 128; n0 = nt * 128; nValid = 1024; cld = 1024;
        Cd = half ? p.RZP1 : p.RZP0;
    } else if (cid < 80) {
        int idx = cid - 64, m = idx & 3, nt = idx >> 2;
        Wd = p.WFN; ldW = 1024; wLoD = 512; wHi = 0; aHi = 0;
        m0 = m * 128; n0 = nt * 128; nValid = 512; cld = 512;
        Cd = p.GI0N;
    } else if (cid < 96) {
        int idx = cid - 80, m = idx & 3, nt = idx >> 2;
        Wd = p.WH0N; ldW = 1024; wLoD = 512; wHi = 0; aHi = 512;
        m0 = m * 128; n0 = nt * 128; nValid = 512; cld = 512;
        Cd = p.GH0N;
    } else if (cid < 144) {
        int idx = cid - 96, m = idx & 3, nt = idx >> 2;
        Wd = p.WGH1; ldW = 1024; wLoD = 512; wHi = 0; aHi = 0;
        m0 = m * 128; n0 = nt * 128; nValid = 1536; cld = 1536;
        Cd = p.GH1;
    } else {
        int m = cid - 144;
        Wd = p.WOUT; ldW = 1024; wLoD = 512; wHi = 0; aHi = 0;
        m0 = m * 128; n0 = 0; nValid = VV; cld = 0;
        isOut = true;
    }
    // ---- phase-B tile descriptor (cid < 96) ----
    int bm0 = 0, bn0 = 0, bk0 = 0;
    float* bC = nullptr;
    if (cid < 96) {
        int m = cid & 3, q = cid >> 2;
        int nt = q % 12, half = q / 12;
        bm0 = m * 128; bn0 = nt * 128; bk0 = half * 256;
        bC = half ? p.GI1P1 : p.GI1P0;
    }

    for (int t = 0; t <= SEQL; t++) {
        // phase A
        if (isOut) {
            if (t >= 1) {
                gemm_tile_p(p.ACAT, Wd, ldW, wLoD, aHi, wHi, 0, 16,
                            m0, n0, nValid, sb, tid, acc);
                epi_out_p(acc, p.dfc2b, m0, p.outp, t - 1, tid);
            }
        } else if (t < SEQL) {
            gemm_tile_p(p.ACAT, Wd, ldW, wLoD, aHi, wHi, 0, 16,
                        m0, n0, nValid, sb, tid, acc);
            epi_raw(acc, Cd, cld, m0, n0, nValid, tid);
        }
        if (t == SEQL) break;
        grid_bar();
        combine0_dev(p, t, gid);
        grid_bar();
        if (cid < 96) {
            gemm_tile_p(p.ACAT, p.WIH1, 1024, 512, 512, 0, bk0, 8,
                        bm0, bn0, 1536, sb, tid, acc);
            epi_raw(acc, bC, 1536, bm0, bn0, 1536, tid);
        }
        grid_bar();
        combine1_dev(p, gid);
        grid_bar();
    }
}

// ---------------------------------------------------------------- encoder GEMM
struct Chunk {
    const __nv_bfloat16* A;
    const __nv_bfloat16* W;
    const float* bias;
    float* C;
    __nv_bfloat16* Cs;
    int N;
    int ldc;
    int mode;   // 1=fp32 out, 2=split out, 4=relu
    int ntiles;
};
struct GemmArgs {
    Chunk ch[2];
    int K;
};

#define NSTAGE 4
#define SMEM64 (NSTAGE * (64 + 128) * ROWB)

__global__ void __launch_bounds__(512) gemm_mma64(GemmArgs args) {
    constexpr int BM = 64;
    constexpr int STB64 = (BM + 128) * ROWB;
    extern __shared__ __align__(128) char smbuf[];
    const uint32_t sb = smem_u32(smbuf);
    const int tid = threadIdx.x;
    const int lane = tid & 31, wid = tid >> 5;
    const int wmBase = (wid >> 2) * 16;
    const int wnBase = (wid & 3) * 32;

    int rem = blockIdx.y, ci = 0;
    while (rem >= args.ch[ci].ntiles) { rem -= args.ch[ci].ntiles; ci++; }
    const Chunk c = args.ch[ci];
    const int n0 = rem * 128;
    const int m0 = blockIdx.x * BM;
    const int K = args.K;
    const int ksub = K >> 5;
    const int Kt = 3 * ksub;
    const int ld2 = 2 * K;

    auto issue = [&](int kt) {
        const int seg = (kt >= 2 * ksub) ? 2 : (kt >= ksub) ? 1 : 0;
        const int kk = kt - seg * ksub;
        const int aCol = kk * 32 + (seg == 1 ? K : 0);
        const int bCol = kk * 32 + (seg == 2 ? K : 0);
        const uint32_t sA = sb + (kt & 3) * STB64;
        const uint32_t sB = sA + BM * ROWB;
        const int row = tid >> 2, ch = tid & 3;
        if (tid < 256)
            cp16(sA + row * ROWB + ch * 16,
                 c.A + (size_t)(m0 + row) * ld2 + aCol + ch * 8);
        {
            int n = n0 + row;
            int ok = (n < c.N);
            cp16z(sB + row * ROWB + ch * 16,
                  c.W + (size_t)(ok ? n : 0) * ld2 + bCol + ch * 8, ok ? 16 : 0);
        }
        asm volatile("cp.async.commit_group;\n" ::: "memory");
    };

    float acc[1][4][4];
#pragma unroll
    for (int ni = 0; ni < 4; ni++)
#pragma unroll
        for (int q = 0; q < 4; q++) acc[0][ni][q] = 0.f;

    issue(0); issue(1); issue(2);
    for (int kt = 0; kt < Kt; kt++) {
        asm volatile("cp.async.wait_group 2;\n" ::: "memory");
        __syncthreads();
        if (kt + 3 < Kt) issue(kt + 3);
        else asm volatile("cp.async.commit_group;\n" ::: "memory");

        const uint32_t sA = sb + (kt & 3) * STB64;
        const uint32_t sB = sA + BM * ROWB;
#pragma unroll
        for (int kh = 0; kh < 2; kh++) {
            uint32_t a[1][4], b[2][4];
            {
                uint32_t addr = sA + (wmBase + (lane & 15)) * ROWB
                              + kh * 32 + ((lane >> 4) * 16);
                ldm4(a[0], addr);
            }
#pragma unroll
            for (int nj = 0; nj < 2; nj++) {
                int grp = lane >> 3;
                int nrow = wnBase + nj * 16 + ((grp >> 1) * 8) + (lane & 7);
                uint32_t addr = sB + nrow * ROWB + (kh * 16 + (grp & 1) * 8) * 2;
                ldm4(b[nj], addr);
            }
#pragma unroll
            for (int ni = 0; ni < 4; ni++)
                mma16816(acc[0][ni], a[0],
                         b[ni >> 1][(ni & 1) * 2], b[ni >> 1][(ni & 1) * 2 + 1]);
        }
    }

    const bool wf  = (c.mode & 1) != 0;
    const bool wsp = (c.mode & 2) != 0;
    const bool rel = (c.mode & 4) != 0;
    {
        const int mrow = m0 + wmBase + (lane >> 2);
#pragma unroll
        for (int ni = 0; ni < 4; ni++) {
            const int n = n0 + wnBase + ni * 8 + (lane & 3) * 2;
#pragma unroll
            for (int half = 0; half < 2; half++) {
                const int mm = mrow + half * 8;
                float v0 = acc[0][ni][half * 2 + 0];
                float v1 = acc[0][ni][half * 2 + 1];
                if (n < c.N) v0 += c.bias[n];
                if (n + 1 < c.N) v1 += c.bias[n + 1];
                if (rel) { v0 = fmaxf(v0, 0.f); v1 = fmaxf(v1, 0.f); }
                if (wf) {
                    if (n < c.N)     c.C[(size_t)mm * c.ldc + n]     = v0;
                    if (n + 1 < c.N) c.C[(size_t)mm * c.ldc + n + 1] = v1;
                }
                if (wsp && n + 1 < c.N) {
                    __nv_bfloat16 h0 = __float2bfloat16(v0);
                    __nv_bfloat16 h1 = __float2bfloat16(v1);
                    __nv_bfloat16 l0 = __float2bfloat16(v0 - __bfloat162float(h0));
                    __nv_bfloat16 l1 = __float2bfloat16(v1 - __bfloat162float(h1));
                    __nv_bfloat162 hv; hv.x = h0; hv.y = h1;
                    __nv_bfloat162 lv2; lv2.x = l0; lv2.y = l1;
                    *(__nv_bfloat162*)(c.Cs + (size_t)mm * (2 * c.N) + n) = hv;
                    *(__nv_bfloat162*)(c.Cs + (size_t)mm * (2 * c.N) + c.N + n) = lv2;
                }
            }
        }
    }
}

// ---------------------------------------------------------------- prep kernels
__global__ void split_k(const float* __restrict__ src, __nv_bfloat16* __restrict__ dst,
                        int R, int C) {
    int i = blockIdx.x * blockDim.x + threadIdx.x;
    if (i >= R * C) return;
    int r = i / C, cc = i % C;
    float x = src[i];
    __nv_bfloat16 h = __float2bfloat16(x);
    dst[(size_t)r * 2 * C + cc] = h;
    dst[(size_t)r * 2 * C + C + cc] = __float2bfloat16(x - __bfloat162float(h));
}

__global__ void fuse_w_k(const float* __restrict__ w_ih0, const float* __restrict__ d_fc2w,
                         const float* __restrict__ d_fc2b, const float* __restrict__ b_ih0,
                         float* __restrict__ Wf, float* __restrict__ bf) {
    __shared__ float w[VV];
    int j = blockIdx.x;
    if (threadIdx.x < VV) w[threadIdx.x] = w_ih0[j * VV + threadIdx.x];
    __syncthreads();
    for (int k = threadIdx.x; k < HH; k += blockDim.x) {
        float s = 0.f;
#pragma unroll
        for (int v = 0; v < VV; v++) s = fmaf(w[v], d_fc2w[v * HH + k], s);
        Wf[(size_t)j * HH + k] = s;
    }
    if (threadIdx.x == 0) {
        float s = b_ih0[j];
#pragma unroll
        for (int v = 0; v < VV; v++) s = fmaf(w[v], d_fc2b[v], s);
        bf[j] = s;
    }
}

__global__ void pack_rz(const float* __restrict__ Wf, const float* __restrict__ whh0,
                        __nv_bfloat16* __restrict__ WRZ) {
    int i = blockIdx.x * blockDim.x + threadIdx.x;
    if (i >= 1024 * 1024) return;
    int jr = i >> 10, c = i & 1023;
    float v = (c < 512) ? Wf[(size_t)jr * 512 + c] : whh0[(size_t)jr * 512 + (c - 512)];
    __nv_bfloat16 hi = __float2bfloat16(v);
    WRZ[(size_t)jr * 2048 + c] = hi;
    WRZ[(size_t)jr * 2048 + 1024 + c] = __float2bfloat16(v - __bfloat162float(hi));
}

__global__ void pack512(const float* __restrict__ src, __nv_bfloat16* __restrict__ dst,
                        int rows) {
    int i = blockIdx.x * blockDim.x + threadIdx.x;
    if (i >= rows * 512) return;
    int r = i >> 9, c = i & 511;
    float v = src[i];
    __nv_bfloat16 hi = __float2bfloat16(v);
    dst[(size_t)r * 1024 + c] = hi;
    dst[(size_t)r * 1024 + 512 + c] = __float2bfloat16(v - __bfloat162float(hi));
}

__global__ void build_bias_p(const float* __restrict__ bf, const float* __restrict__ w_ih0,
                             const float* __restrict__ b_ih0, const float* __restrict__ b_hh0,
                             float* __restrict__ brz0, float* __restrict__ brz,
                             float* __restrict__ bgin0, float* __restrict__ bgin,
                             float* __restrict__ bghn) {
    int r = blockIdx.x * blockDim.x + threadIdx.x;
    if (r < 1024) {
        brz0[r] = w_ih0[(size_t)r * VV + (VV - 1)] + b_ih0[r] + b_hh0[r];
        brz[r]  = bf[r] + b_hh0[r];
    }
    if (r < 512) {
        bgin0[r] = w_ih0[(size_t)(1024 + r) * VV + (VV - 1)] + b_ih0[1024 + r];
        bgin[r]  = bf[1024 + r];
        bghn[r]  = b_hh0[1024 + r];
    }
}

__global__ void kld_kernel(const float* __restrict__ mu, const float* __restrict__ lv,
                           float* __restrict__ out) {
    __shared__ float red[1024];
    float s = 0.f;
    for (int i = threadIdx.x; i < BB * ENCD; i += blockDim.x) {
        float m = mu[i], l = lv[i];
        s += 1.f + l - m * m - expf(l);
    }
    red[threadIdx.x] = s;
    __syncthreads();
    for (int off = 512; off > 0; off >>= 1) {
        if (threadIdx.x < off) red[threadIdx.x] += red[threadIdx.x + off];
        __syncthreads();
    }
    if (threadIdx.x == 0) out[0] = -0.5f * red[0] / (float)BB;
}

__global__ void reparam_k(const float* __restrict__ eps, const float* __restrict__ mu,
                          const float* __restrict__ lv, __nv_bfloat16* __restrict__ encs) {
    int i = blockIdx.x * blockDim.x + threadIdx.x;
    if (i >= BB * ENCD) return;
    float v = eps[i] * expf(0.5f * lv[i]) + mu[i];
    int b = i / ENCD, j = i % ENCD;
    __nv_bfloat16 h = __float2bfloat16(v);
    encs[(size_t)b * 2 * ENCD + j] = h;
    encs[(size_t)b * 2 * ENCD + ENCD + j] = __float2bfloat16(v - __bfloat162float(h));
}

__global__ void init_state_p(const float* __restrict__ h0f, __nv_bfloat16* __restrict__ ACAT,
                             float* __restrict__ h1f) {
    int i = blockIdx.x * blockDim.x + threadIdx.x;
    if (i >= BB * HH) return;
    int m = i >> 9, j = i & 511;
    float v = h0f[i];
    __nv_bfloat16 hi = __float2bfloat16(v);
    __nv_bfloat16 lo = __float2bfloat16(v - __bfloat162float(hi));
    __nv_bfloat16 z = __float2bfloat16(0.f);
    size_t row = (size_t)m * 2048;
    ACAT[row + j] = z;          // h1 hi
    ACAT[row + 1024 + j] = z;   // h1 lo
    ACAT[row + 512 + j] = hi;   // h0 hi
    ACAT[row + 1536 + j] = lo;  // h0 lo
    h1f[i] = 0.f;
}

// ---------------------------------------------------------------- launcher
static inline void launch64(const GemmArgs& a, int nch) {
    int ny = 0;
    for (int i = 0; i < nch; i++) ny += a.ch[i].ntiles;
    gemm_mma64<<<dim3(8, ny), 512, SMEM64>>>(a);
}

extern "C" void kernel_launch(void* const* d_in, const int* in_sizes, int n_in,
                              void* d_out, int out_size) {
    const float* X       = (const float*)d_in[0];
    const float* eps     = (const float*)d_in[2];
    const float* e_fc1w  = (const float*)d_in[3];
    const float* e_fc1b  = (const float*)d_in[4];
    const float* e_fc2w  = (const float*)d_in[5];
    const float* e_fc2b  = (const float*)d_in[6];
    const float* e_fc3w  = (const float*)d_in[7];
    const float* e_fc3b  = (const float*)d_in[8];
    const float* e_fc41w = (const float*)d_in[9];
    const float* e_fc41b = (const float*)d_in[10];
    const float* e_fc42w = (const float*)d_in[11];
    const float* e_fc42b = (const float*)d_in[12];
    const float* d_fc1w  = (const float*)d_in[13];
    const float* d_fc1b  = (const float*)d_in[14];
    const float* d_fc2w  = (const float*)d_in[15];
    const float* d_fc2b  = (const float*)d_in[16];
    const float* w_ih0   = (const float*)d_in[17];
    const float* b_ih0   = (const float*)d_in[18];
    const float* w_hh0   = (const float*)d_in[19];
    const float* b_hh0   = (const float*)d_in[20];
    const float* w_ih1   = (const float*)d_in[21];
    const float* b_ih1   = (const float*)d_in[22];
    const float* w_hh1   = (const float*)d_in[23];
    const float* b_hh1   = (const float*)d_in[24];

    float* out = (float*)d_out;
    float* kld_out = out + (size_t)BB * SEQL * VV;

    cudaFuncSetAttribute(gemm_mma64, cudaFuncAttributeMaxDynamicSharedMemorySize, SMEM64);
    cudaFuncSetAttribute(decoder_persist, cudaFuncAttributeMaxDynamicSharedMemorySize,
                         PERSIST_SMEM);

    float* F = nullptr;
    __nv_bfloat16* Sb = nullptr;
    cudaGetSymbolAddress((void**)&F, g_f32);
    cudaGetSymbolAddress((void**)&Sb, g_bf);

    float* mu   = F + F_MU;
    float* lv   = F + F_LV;
    float* h0f  = F + F_H0F;
    float* h1f  = F + F_H1F;
    float* Wfp  = F + F_WFP;
    float* bf   = F + F_BF;

    __nv_bfloat16* Xs    = Sb + S_XS;
    __nv_bfloat16* e1ws  = Sb + S_E1WS;
    __nv_bfloat16* h1es  = Sb + S_H1ES;
    __nv_bfloat16* e2ws  = Sb + S_E2WS;
    __nv_bfloat16* h2es  = Sb + S_H2ES;
    __nv_bfloat16* e3ws  = Sb + S_E3WS;
    __nv_bfloat16* h3es  = Sb + S_H3ES;
    __nv_bfloat16* e41s  = Sb + S_E41S;
    __nv_bfloat16* e42s  = Sb + S_E42S;
    __nv_bfloat16* encs  = Sb + S_ENCS;
    __nv_bfloat16* dfc1s = Sb + S_DFC1S;

    auto split = [&](const float* s, __nv_bfloat16* d, int R, int C) {
        int n = R * C;
        split_k<<<(n + 255) / 256, 256>>>(s, d, R, C);
    };

    // ---- decoder weight prep ----
    fuse_w_k<<<H3, 256>>>(w_ih0, d_fc2w, d_fc2b, b_ih0, Wfp, bf);
    pack_rz<<<(1024 * 1024 + 255) / 256, 256>>>(Wfp, w_hh0, Sb + S_WRZ);
    pack512<<<(512 * 512 + 255) / 256, 256>>>(Wfp + 1024 * 512, Sb + S_WFN, 512);
    pack512<<<(512 * 512 + 255) / 256, 256>>>(w_hh0 + 1024 * 512, Sb + S_WH0N, 512);
    pack512<<<(1536 * 512 + 255) / 256, 256>>>(w_hh1, Sb + S_WGH1, 1536);
    pack512<<<(1536 * 512 + 255) / 256, 256>>>(w_ih1, Sb + S_WIH1, 1536);
    pack512<<<(42 * 512 + 255) / 256, 256>>>(d_fc2w, Sb + S_WOUT, 42);
    build_bias_p<<<4, 256>>>(bf, w_ih0, b_ih0, b_hh0,
                             F + F_BRZ0, F + F_BRZ, F + F_BGIN0, F + F_BGIN, F + F_BGHN);

    // ---- encoder ----
    split(X, Xs, BB, FP);
    split(e_fc1w, e1ws, 2048, FP);
    split(e_fc2w, e2ws, 1024, 2048);
    split(e_fc3w, e3ws, 512, 1024);
    split(e_fc41w, e41s, ENCD, 512);
    split(e_fc42w, e42s, ENCD, 512);
    split(d_fc1w, dfc1s, HH, ENCD);

    {
        GemmArgs a{}; a.K = FP;
        a.ch[0] = {Xs, e1ws, e_fc1b, nullptr, h1es, 2048, 0, 2 | 4, 16};
        launch64(a, 1);
    }
    {
        GemmArgs a{}; a.K = 2048;
        a.ch[0] = {h1es, e2ws, e_fc2b, nullptr, h2es, 1024, 0, 2 | 4, 8};
        launch64(a, 1);
    }
    {
        GemmArgs a{}; a.K = 1024;
        a.ch[0] = {h2es, e3ws, e_fc3b, nullptr, h3es, 512, 0, 2 | 4, 4};
        launch64(a, 1);
    }
    {
        GemmArgs a{}; a.K = 512;
        a.ch[0] = {h3es, e41s, e_fc41b, mu, nullptr, ENCD, ENCD, 1, 1};
        a.ch[1] = {h3es, e42s, e_fc42b, lv, nullptr, ENCD, ENCD, 1, 1};
        launch64(a, 2);
    }
    kld_kernel<<<1, 1024>>>(mu, lv, kld_out);
    reparam_k<<<(BB * ENCD + 255) / 256, 256>>>(eps, mu, lv, encs);
    {
        GemmArgs a{}; a.K = ENCD;
        a.ch[0] = {encs, dfc1s, d_fc1b, h0f, nullptr, HH, HH, 1, 4};
        launch64(a, 1);
    }
    init_state_p<<<(BB * HH + 255) / 256, 256>>>(h0f, Sb + S_ACAT, h1f);

    // ---- persistent decoder ----
    DP p{};
    p.ACAT = Sb + S_ACAT;
    p.WRZ = Sb + S_WRZ; p.WFN = Sb + S_WFN; p.WH0N = Sb + S_WH0N;
    p.WGH1 = Sb + S_WGH1; p.WIH1 = Sb + S_WIH1; p.WOUT = Sb + S_WOUT;
    p.RZP0 = F + F_RZP0; p.RZP1 = F + F_RZP1;
    p.GI0N = F + F_GI0N; p.GH0N = F + F_GH0N; p.GH1 = F + F_GH1;
    p.GI1P0 = F + F_GI1P0; p.GI1P1 = F + F_GI1P1;
    p.brz0 = F + F_BRZ0; p.brz = F + F_BRZ;
    p.bgin0 = F + F_BGIN0; p.bgin = F + F_BGIN; p.bghn = F + F_BGHN;
    p.bih1 = b_ih1; p.bhh1 = b_hh1; p.dfc2b = d_fc2b;
    p.h0f = h0f; p.h1f = h1f; p.outp = out;
    decoder_persist<<<GRID_N, 512, PERSIST_SMEM>>>(p);
}